// round 10
// baseline (speedup 1.0000x reference)
#include <cuda_runtime.h>
#include <cstdint>

// ---------------- config ----------------
#define GRIDX 296              // 2 x 148, resident with (256,2)
#define WPB   8                // warps per block
#define TILE  32               // samples per warp-tile
#define BUFW  688              // words per tile buffer (672 + pad)

// ---------------- device scratch ----------------
__device__ float    g_part[GRIDX * 8];   // [blk][0..3]=S, [4..7]=Q
__device__ float    g_scale[8];
__device__ unsigned g_cnt  = 0;
__device__ unsigned g_flag = 0;

__device__ __forceinline__ void cp16(float* dst_smem, const float4* src_gmem) {
    unsigned d = (unsigned)__cvta_generic_to_shared(dst_smem);
    asm volatile("cp.async.cg.shared.global [%0], [%1], 16;\n"
                 :: "r"(d), "l"(src_gmem));
}

struct cf { float re, im; };
__device__ __forceinline__ cf cmul(cf a, cf b) { return {a.re*b.re - a.im*b.im, a.re*b.im + a.im*b.re}; }
__device__ __forceinline__ cf cadd(cf a, cf b) { return {a.re + b.re, a.im + b.im}; }

__global__ __launch_bounds__(256, 2) void k_all(
    const float* __restrict__ x, const float* __restrict__ W,
    const float* __restrict__ b, const float* __restrict__ vp,
    const float* __restrict__ gamma, const float* __restrict__ beta,
    float* __restrict__ out, int B)
{
    extern __shared__ float tb[];              // [WPB][2][BUFW] = 44032 B
    __shared__ float  sPooled[WPB * 544];      // [warp][sample*17 + bin]
    __shared__ float4 sUf4[128];               // [p*8+jp]: U'[p][2jp],U'[p][2jp+1]
    __shared__ float4 sW[16];                  // W rows
    __shared__ float  sPart[WPB][8];
    __shared__ float  sScale[8];
    __shared__ unsigned sTicket;

    const int tid  = threadIdx.x;
    const int w    = tid >> 5;
    const int lane = tid & 31;
    const int h    = lane >> 4;
    const int q    = lane & 15;
    const int bid  = blockIdx.x;

    const unsigned epoch = *(volatile unsigned*)&g_flag;

    const float4* xv = reinterpret_cast<const float4*>(x);
    const int nTiles = B / TILE;

    float* myBuf = tb + w * (2 * BUFW);

    auto issue = [&](long s, int buf) {        // stage sample s: 168 f4 coalesced
        const float4* src = xv + s * 196;
        float* dst = myBuf + buf * BUFW;
        #pragma unroll
        for (int k = 0; k < 5; k++) cp16(dst + (k*32 + lane)*4, src + k*32 + lane);
        if (lane < 8) cp16(dst + (160 + lane)*4, src + 160 + lane);
        asm volatile("cp.async.commit_group;\n");
    };

    // ---- prologue: first tile's sample 0 (if this warp has work) ----
    const int t0 = bid + GRIDX * w;
    if (t0 < nTiles) issue((long)t0 * TILE, 0);

    // ---- warp 0 builds pre-rotated U; lanes 16..31 load W ----
    if (tid < 16) {
        const int j = tid;                     // column
        cf st[16];
        #pragma unroll
        for (int i = 0; i < 16; i++) st[i] = { (i == j) ? 1.0f : 0.0f, 0.0f };
        for (int l = 0; l < 3; l++) {
            for (int ww = 0; ww < 4; ww++) {
                float tx = vp[(l*4 + ww)*3 + 0];
                float ty = vp[(l*4 + ww)*3 + 1];
                float tz = vp[(l*4 + ww)*3 + 2];
                float cx, sx, cy, sy, cz, sz;
                sincosf(tx*0.5f, &sx, &cx);
                sincosf(ty*0.5f, &sy, &cy);
                sincosf(tz*0.5f, &sz, &cz);
                cf M00{ cy*cx,  sy*sx }, M01{ -sy*cx, -cy*sx };
                cf M10{ sy*cx, -cy*sx }, M11{  cy*cx, -sy*sx };
                cf e0{ cz, -sz }, e1{ cz, sz };
                cf G00 = cmul(e0, M00), G01 = cmul(e0, M01);
                cf G10 = cmul(e1, M10), G11 = cmul(e1, M11);
                int mask = 8 >> ww;
                #pragma unroll
                for (int i = 0; i < 16; i++) {
                    if (i & mask) continue;
                    cf a0 = st[i], a1 = st[i | mask];
                    st[i]        = cadd(cmul(G00, a0), cmul(G01, a1));
                    st[i | mask] = cadd(cmul(G10, a0), cmul(G11, a1));
                }
            }
            for (int ww = 0; ww < 3; ww++) {   // CNOT chain
                int cm = 8 >> ww, tm = 4 >> ww;
                cf tmp[16];
                #pragma unroll
                for (int i = 0; i < 16; i++) tmp[i] = st[(i & cm) ? (i ^ tm) : i];
                #pragma unroll
                for (int i = 0; i < 16; i++) st[i] = tmp[i];
            }
        }
        const int pm = __popc(j) & 3;          // bake in (-i)^popc(j)
        float2* uw = reinterpret_cast<float2*>(sUf4);
        const int jp = j >> 1, jl = j & 1;
        #pragma unroll
        for (int i = 0; i < 16; i++) {
            float r = st[i].re, im = st[i].im, nr, ni;
            if      (pm == 0) { nr =  r;  ni =  im; }
            else if (pm == 1) { nr =  im; ni = -r;  }
            else if (pm == 2) { nr = -r;  ni = -im; }
            else              { nr = -im; ni =  r;  }
            uw[(i*8 + jp)*2 + jl] = make_float2(nr, ni);
        }
    } else if (tid < 32) {
        sW[tid - 16] = reinterpret_cast<const float4*>(W)[tid - 16];
    }
    __syncthreads();

    const float4 bv = *reinterpret_cast<const float4*>(b);

    const int cb = q & 3, rb = q >> 2;
    const int poolBase = (rb*6 + h*3)*28 + cb*6;   // this half's 3 rows of bin q

    float runS0=0, runS1=0, runS2=0, runS3=0;
    float runQ0=0, runQ1=0, runQ2=0, runQ3=0;

    for (int t = t0; t < nTiles; t += GRIDX * WPB) {
        const long sBase = (long)t * TILE;

        // ================= Phase A: pooling, 32 steps =================
        for (int k = 0; k < TILE; k++) {
            if (k + 1 < TILE) {
                issue(sBase + k + 1, (k + 1) & 1);
                asm volatile("cp.async.wait_group 1;\n");
            } else {
                asm volatile("cp.async.wait_group 0;\n");
            }
            __syncwarp();

            const float* sf = myBuf + (k & 1) * BUFW + poolBase;
            float acc = 0.f;
            #pragma unroll
            for (int r = 0; r < 3; r++) {
                const float2* rp = reinterpret_cast<const float2*>(sf + r*28);
                acc += rp[0].x + rp[0].y + rp[1].x + rp[1].y + rp[2].x + rp[2].y;
            }
            float v = acc + __shfl_xor_sync(0xffffffffu, acc, 16);
            v *= (1.0f / 36.0f);
            if (h == 0) sPooled[w*544 + k*17 + q] = v;
            __syncwarp();
        }

        // ================= Phase B: lane = sample, shuffle-free =======
        {
            const float* pw = sPooled + w*544 + lane*17;
            float pl[16];
            #pragma unroll
            for (int k2 = 0; k2 < 16; k2++) pl[k2] = pw[k2];

            float f0 = bv.x, f1 = bv.y, f2 = bv.z, f3 = bv.w;
            #pragma unroll
            for (int k2 = 0; k2 < 16; k2++) {
                float4 wr = sW[k2];
                f0 += pl[k2]*wr.x; f1 += pl[k2]*wr.y;
                f2 += pl[k2]*wr.z; f3 += pl[k2]*wr.w;
            }

            float c0_,s_0,c1_,s_1,c2_,s_2,c3_,s_3;
            __sincosf(0.5f*f0, &s_0, &c0_);
            __sincosf(0.5f*f1, &s_1, &c1_);
            __sincosf(0.5f*f2, &s_2, &c2_);
            __sincosf(0.5f*f3, &s_3, &c3_);
            float w01v[4] = { c0_*c1_, c0_*s_1, s_0*c1_, s_0*s_1 };
            float w23v[4] = { c2_*c3_, c2_*s_3, s_2*c3_, s_2*s_3 };
            float m[16];
            #pragma unroll
            for (int j = 0; j < 16; j++) m[j] = w01v[j >> 2] * w23v[j & 3];

            float z0=0, z1=0, z2=0, z3=0;
            #pragma unroll
            for (int p = 0; p < 16; p++) {
                float ar = 0.f, ai = 0.f, ar2 = 0.f, ai2 = 0.f;
                #pragma unroll
                for (int jp = 0; jp < 8; jp += 2) {
                    float4 u  = sUf4[p*8 + jp];
                    float4 u2 = sUf4[p*8 + jp + 1];
                    ar  += u.x *m[2*jp]   + u.z *m[2*jp+1];
                    ai  += u.y *m[2*jp]   + u.w *m[2*jp+1];
                    ar2 += u2.x*m[2*jp+2] + u2.z*m[2*jp+3];
                    ai2 += u2.y*m[2*jp+2] + u2.w*m[2*jp+3];
                }
                ar += ar2; ai += ai2;
                float prob = ar*ar + ai*ai;
                z0 += (p & 8) ? -prob : prob;
                z1 += (p & 4) ? -prob : prob;
                z2 += (p & 2) ? -prob : prob;
                z3 += (p & 1) ? -prob : prob;
            }

            reinterpret_cast<float4*>(out)[sBase + lane] = make_float4(z0, z1, z2, z3);
            runS0 += z0; runS1 += z1; runS2 += z2; runS3 += z3;
            runQ0 += z0*z0; runQ1 += z1*z1; runQ2 += z2*z2; runQ3 += z3*z3;
        }
        __syncwarp();
    }

    // ---- warp-reduce stats across 32 lanes ----
    #pragma unroll
    for (int mm = 1; mm < 32; mm <<= 1) {
        runS0 += __shfl_xor_sync(0xffffffffu, runS0, mm);
        runS1 += __shfl_xor_sync(0xffffffffu, runS1, mm);
        runS2 += __shfl_xor_sync(0xffffffffu, runS2, mm);
        runS3 += __shfl_xor_sync(0xffffffffu, runS3, mm);
        runQ0 += __shfl_xor_sync(0xffffffffu, runQ0, mm);
        runQ1 += __shfl_xor_sync(0xffffffffu, runQ1, mm);
        runQ2 += __shfl_xor_sync(0xffffffffu, runQ2, mm);
        runQ3 += __shfl_xor_sync(0xffffffffu, runQ3, mm);
    }
    if (lane == 0) {
        sPart[w][0] = runS0; sPart[w][1] = runS1;
        sPart[w][2] = runS2; sPart[w][3] = runS3;
        sPart[w][4] = runQ0; sPart[w][5] = runQ1;
        sPart[w][6] = runQ2; sPart[w][7] = runQ3;
    }
    __syncthreads();

    if (tid < 8) {
        float tt = 0.f;
        #pragma unroll
        for (int k = 0; k < WPB; k++) tt += sPart[k][tid];
        g_part[bid * 8 + tid] = tt;
    }
    __threadfence();
    if (tid == 0) sTicket = atomicAdd(&g_cnt, 1u);
    __syncthreads();

    if ((sTicket % GRIDX) == GRIDX - 1) {
        __threadfence();
        float* sRed = reinterpret_cast<float*>(sUf4);   // 512-float scratch
        {
            int ch = tid & 7, row = tid >> 3;            // 32 rows x 8 channels
            float s = 0.f;
            for (int p2 = row; p2 < GRIDX; p2 += 32) s += __ldcg(&g_part[p2*8 + ch]);
            sRed[row*8 + ch] = s;
        }
        __syncthreads();
        if (tid < 8) {
            float tt = 0.f;
            #pragma unroll
            for (int r = 0; r < 32; r++) tt += sRed[r*8 + tid];
            sRed[256 + tid] = tt;
        }
        __syncthreads();
        if (tid < 4) {
            float invB = 1.0f / (float)B;
            float mu  = sRed[256 + tid] * invB;
            float var = sRed[260 + tid] * invB - mu*mu;    // biased var
            float scw = gamma[tid] * rsqrtf(var + 1e-5f);
            g_scale[tid]     = scw;
            g_scale[4 + tid] = beta[tid] - mu * scw;
        }
        __threadfence();
        __syncthreads();
        if (tid == 0) atomicAdd(&g_flag, 1u);
    }

    if (tid == 0) {
        while (*(volatile unsigned*)&g_flag == epoch) __nanosleep(64);
    }
    __syncthreads();
    __threadfence();

    if (tid < 8) sScale[tid] = *(volatile float*)&g_scale[tid];
    __syncthreads();

    // ---- normalize: one f4 per thread, coalesced ----
    {
        float4 scv = *reinterpret_cast<const float4*>(&sScale[0]);
        float4 shv = *reinterpret_cast<const float4*>(&sScale[4]);
        for (long i = (long)bid * 256 + tid; i < B; i += (long)GRIDX * 256) {
            float4 r = reinterpret_cast<float4*>(out)[i];
            r.x = r.x*scv.x + shv.x;
            r.y = r.y*scv.y + shv.y;
            r.z = r.z*scv.z + shv.z;
            r.w = r.w*scv.w + shv.w;
            reinterpret_cast<float4*>(out)[i] = r;
        }
    }
}

// ---------------- launch ----------------------------------------------------
extern "C" void kernel_launch(void* const* d_in, const int* in_sizes, int n_in,
                              void* d_out, int out_size)
{
    const float* x     = (const float*)d_in[0];  // [B,1,28,28]
    const float* W     = (const float*)d_in[1];  // [16,4]
    const float* b     = (const float*)d_in[2];  // [4]
    const float* vp    = (const float*)d_in[3];  // [3,4,3]
    const float* gamma = (const float*)d_in[4];  // [4]
    const float* beta  = (const float*)d_in[5];  // [4]
    float* out = (float*)d_out;                  // [B,4]

    int B = in_sizes[0] / 784;                   // 65536

    const int dynBytes = WPB * 2 * BUFW * 4;     // 44032
    cudaFuncSetAttribute(k_all, cudaFuncAttributeMaxDynamicSharedMemorySize, dynBytes);
    k_all<<<GRIDX, 256, dynBytes>>>(x, W, b, vp, gamma, beta, out, B);
}